// round 8
// baseline (speedup 1.0000x reference)
#include <cuda_runtime.h>
#include <cuda_fp16.h>
#include <cstdint>

#define BATCH   2048
#define INSZ    40960
#define KC      64
#define KSTPT   640                 // k-stages per tile (40960/64)
#define NTILE   64                  // 2 persp x 16 mt x 2 nt
#define TOTS    (NTILE * KSTPT)     // 40960 stage-units
#define ASTRW   36                  // smem row stride in words (64 fp16 + pad)
#define A_WORDS (128 * ASTRW)
#define BUF_WORDS (2 * A_WORDS)
#define SMEM_BYTES (2 * BUF_WORDS * 4)   // 73728

// tail smem carve (floats)
#define TW2_STRIDE 516
#define TW2_FLOATS (32 * TW2_STRIDE)
#define TCOMB_STRIDE 516
#define TCOMB_FLOATS (8 * TCOMB_STRIDE)
#define TH1_FLOATS (8 * 32)
#define TAIL_SMEM_BYTES ((TW2_FLOATS + TCOMB_FLOATS + TH1_FLOATS) * 4)

// partials: [tile][slot(4)][m_local(128)][n_local(128)] = 16 MB
__device__ float g_partial[(size_t)NTILE * 4 * 128 * 128];

__device__ __forceinline__ float crelu(float x) { return fminf(fmaxf(x, 0.f), 1.f); }

__device__ __forceinline__ uint32_t f2h2(float a, float b) {
    __half2 h = __floats2half2_rn(a, b);
    return *reinterpret_cast<uint32_t*>(&h);
}

// fp16-accumulate MMA: D(half2 x2) = A*B + D
__device__ __forceinline__ void mma16h(uint32_t& d0, uint32_t& d1,
                                       uint32_t a0, uint32_t a1, uint32_t a2, uint32_t a3,
                                       uint32_t b0, uint32_t b1) {
    asm volatile(
        "mma.sync.aligned.m16n8k16.row.col.f16.f16.f16.f16 "
        "{%0,%1}, {%2,%3,%4,%5}, {%6,%7}, {%0,%1};"
        : "+r"(d0), "+r"(d1)
        : "r"(a0), "r"(a1), "r"(a2), "r"(a3), "r"(b0), "r"(b1));
}

__global__ void zero_kernel() {
    const size_t idx = (size_t)blockIdx.x * 256 + threadIdx.x;
    reinterpret_cast<float4*>(g_partial)[idx] = make_float4(0.f, 0.f, 0.f, 0.f);
}

// ========== Kernel 1: FT GEMM, fp16-accum MMA + per-stage fp32 promotion ==========
__global__ void __launch_bounds__(256, 1)
ft_kernel(const float* __restrict__ xp, const float* __restrict__ xo,
          const float* __restrict__ wp, const float* __restrict__ wo)
{
    extern __shared__ uint32_t sm[];
    const int tid = threadIdx.x, lane = tid & 31, wid = tid >> 5;
    const int G = gridDim.x, ib = blockIdx.x;
    int S = (int)((long)ib * TOTS / G);
    const int S_hi = (int)((long)(ib + 1) * TOTS / G);
    const uint32_t smb = (uint32_t)__cvta_generic_to_shared(sm);
    const int wm = (wid & 3) * 32;
    const int wn = (wid >> 2) * 64;

    while (S < S_hi) {
        const int t    = S / KSTPT;
        const int send = min(S_hi, (t + 1) * KSTPT);
        const int ks0  = S - t * KSTPT;
        const int len  = send - S;
        const int persp = t >> 5, mt = (t >> 1) & 15, nt = t & 1;
        const float* __restrict__ X = persp ? xo : xp;
        const float* __restrict__ W = persp ? wo : wp;
        const int m0 = mt * 128, n0 = nt * 128;
        const size_t kbase = (size_t)ks0 * KC;

        const float* aptr[8]; const float* bptr[8];
        uint32_t asw[8], bsw[8];
        #pragma unroll
        for (int j = 0; j < 8; j++) {
            int f = tid + j * 256, r = f >> 4, q = f & 15;
            aptr[j] = X + (size_t)(m0 + r) * INSZ + kbase + q * 4;
            bptr[j] = W + (size_t)(n0 + r) * INSZ + kbase + q * 4;
            asw[j] = smb + 4u * (r * ASTRW + q * 2);
            bsw[j] = smb + 4u * (A_WORDS + r * ASTRW + q * 2);
        }

        float acc[2][8][4];
        #pragma unroll
        for (int a = 0; a < 2; a++)
            #pragma unroll
            for (int b = 0; b < 8; b++)
                #pragma unroll
                for (int c = 0; c < 4; c++) acc[a][b][c] = 0.f;

        float4 ra[8], rb[8];
        // prologue: stage 0 -> buf0
        #pragma unroll
        for (int j = 0; j < 8; j++) ra[j] = *reinterpret_cast<const float4*>(aptr[j]);
        #pragma unroll
        for (int j = 0; j < 8; j++) rb[j] = *reinterpret_cast<const float4*>(bptr[j]);
        #pragma unroll
        for (int j = 0; j < 8; j++) {
            uint32_t u0 = f2h2(ra[j].x, ra[j].y), u1 = f2h2(ra[j].z, ra[j].w);
            asm volatile("st.shared.v2.b32 [%0], {%1,%2};" :: "r"(asw[j]), "r"(u0), "r"(u1) : "memory");
            uint32_t v0 = f2h2(rb[j].x, rb[j].y), v1 = f2h2(rb[j].z, rb[j].w);
            asm volatile("st.shared.v2.b32 [%0], {%1,%2};" :: "r"(bsw[j]), "r"(v0), "r"(v1) : "memory");
        }
        __syncthreads();
        if (len > 1) {
            #pragma unroll
            for (int j = 0; j < 8; j++) ra[j] = *reinterpret_cast<const float4*>(aptr[j] + KC);
            #pragma unroll
            for (int j = 0; j < 8; j++) rb[j] = *reinterpret_cast<const float4*>(bptr[j] + KC);
        }

        for (int s2 = 0; s2 < len; s2++) {
            const int buf = s2 & 1;
            if (s2 + 1 < len) {
                const uint32_t boff = (uint32_t)((buf ^ 1) * BUF_WORDS * 4);
                #pragma unroll
                for (int j = 0; j < 8; j++) {
                    uint32_t u0 = f2h2(ra[j].x, ra[j].y), u1 = f2h2(ra[j].z, ra[j].w);
                    asm volatile("st.shared.v2.b32 [%0], {%1,%2};" :: "r"(asw[j] + boff), "r"(u0), "r"(u1) : "memory");
                    uint32_t v0 = f2h2(rb[j].x, rb[j].y), v1 = f2h2(rb[j].z, rb[j].w);
                    asm volatile("st.shared.v2.b32 [%0], {%1,%2};" :: "r"(bsw[j] + boff), "r"(v0), "r"(v1) : "memory");
                }
            }
            if (s2 + 2 < len) {
                const size_t ko = (size_t)(s2 + 2) * KC;
                #pragma unroll
                for (int j = 0; j < 8; j++) ra[j] = *reinterpret_cast<const float4*>(aptr[j] + ko);
                #pragma unroll
                for (int j = 0; j < 8; j++) rb[j] = *reinterpret_cast<const float4*>(bptr[j] + ko);
            }
            const uint32_t* sa = sm + buf * BUF_WORDS;
            const uint32_t* sb = sa + A_WORDS;

            // fp16 chunk accumulators for this KC=64 stage
            uint32_t hacc[2][8][2];
            #pragma unroll
            for (int a = 0; a < 2; a++)
                #pragma unroll
                for (int b = 0; b < 8; b++) { hacc[a][b][0] = 0u; hacc[a][b][1] = 0u; }

            #pragma unroll
            for (int kk = 0; kk < 4; kk++) {
                const int kw = kk * 8 + (lane & 3);
                uint32_t af[2][4], bf[8][2];
                #pragma unroll
                for (int mtl = 0; mtl < 2; mtl++) {
                    const int r = wm + mtl * 16 + (lane >> 2);
                    af[mtl][0] = sa[r * ASTRW + kw];
                    af[mtl][1] = sa[(r + 8) * ASTRW + kw];
                    af[mtl][2] = sa[r * ASTRW + kw + 4];
                    af[mtl][3] = sa[(r + 8) * ASTRW + kw + 4];
                }
                #pragma unroll
                for (int ntl = 0; ntl < 8; ntl++) {
                    const int rn = wn + ntl * 8 + (lane >> 2);
                    bf[ntl][0] = sb[rn * ASTRW + kw];
                    bf[ntl][1] = sb[rn * ASTRW + kw + 4];
                }
                #pragma unroll
                for (int mtl = 0; mtl < 2; mtl++)
                    #pragma unroll
                    for (int ntl = 0; ntl < 8; ntl++)
                        mma16h(hacc[mtl][ntl][0], hacc[mtl][ntl][1],
                               af[mtl][0], af[mtl][1], af[mtl][2], af[mtl][3],
                               bf[ntl][0], bf[ntl][1]);
            }
            // promote chunk sums to fp32
            #pragma unroll
            for (int mtl = 0; mtl < 2; mtl++)
                #pragma unroll
                for (int ntl = 0; ntl < 8; ntl++) {
                    float2 lo = __half22float2(*reinterpret_cast<__half2*>(&hacc[mtl][ntl][0]));
                    float2 hi = __half22float2(*reinterpret_cast<__half2*>(&hacc[mtl][ntl][1]));
                    acc[mtl][ntl][0] += lo.x;
                    acc[mtl][ntl][1] += lo.y;
                    acc[mtl][ntl][2] += hi.x;
                    acc[mtl][ntl][3] += hi.y;
                }
            __syncthreads();
        }

        // epilogue: deterministic slot = ib - owner(first stage of tile t)
        const int owner0 = (int)(((long)(t * KSTPT + 1) * G + TOTS - 1) / TOTS) - 1;
        const int slot = ib - owner0;       // 0..3
        float* gp = g_partial + ((size_t)t * 4 + slot) * 16384;
        #pragma unroll
        for (int mtl = 0; mtl < 2; mtl++) {
            const int ml = wm + mtl * 16 + (lane >> 2);
            #pragma unroll
            for (int ntl = 0; ntl < 8; ntl++) {
                const int col = wn + ntl * 8 + (lane & 3) * 2;
                *reinterpret_cast<float2*>(&gp[(size_t)ml * 128 + col]) =
                    make_float2(acc[mtl][ntl][0], acc[mtl][ntl][1]);
                *reinterpret_cast<float2*>(&gp[(size_t)(ml + 8) * 128 + col]) =
                    make_float2(acc[mtl][ntl][2], acc[mtl][ntl][3]);
            }
        }
        S = send;
    }
}

// ========== Kernel 2: fused 4-slot reduce + bias + crelu + tail MLP ==========
__global__ void __launch_bounds__(256)
reduce_tail(const float* __restrict__ b1p, const float* __restrict__ b1o,
            const float* __restrict__ W2, const float* __restrict__ b2,
            const float* __restrict__ W3, const float* __restrict__ b3,
            const float* __restrict__ Wo, const float* __restrict__ bo,
            float* __restrict__ out)
{
    extern __shared__ float ts[];
    float* W2s  = ts;                       // [32][516]
    float* comb = ts + TW2_FLOATS;          // [8][516]
    float* h1s  = comb + TCOMB_FLOATS;      // [8][32]
    const int tid = threadIdx.x, lane = tid & 31, wid = tid >> 5;
    const int R0 = blockIdx.x * 8;

    #pragma unroll
    for (int it = 0; it < 4; it++) {
        const int idx = it * 256 + tid;            // 8 rows x 128 f4
        const int row = idx >> 7, fq = idx & 127;
        const int m = R0 + row;
        const int f = fq * 4;
        const int persp = f >> 8;
        const int ntl = (f >> 7) & 1;
        const int c = f & 127;
        const int t = persp * 32 + (m >> 7) * 2 + ntl;
        const float* gp = g_partial + (size_t)t * 4 * 16384 + (size_t)(m & 127) * 128 + c;
        float4 bv = (f < 256) ? *reinterpret_cast<const float4*>(&b1p[f])
                              : *reinterpret_cast<const float4*>(&b1o[f - 256]);
        float4 s = bv;
        #pragma unroll
        for (int sl = 0; sl < 4; sl++) {
            float4 v = *reinterpret_cast<const float4*>(gp + (size_t)sl * 16384);
            s.x += v.x; s.y += v.y; s.z += v.z; s.w += v.w;
        }
        float* cc = comb + row * TCOMB_STRIDE + f;
        cc[0] = crelu(s.x); cc[1] = crelu(s.y); cc[2] = crelu(s.z); cc[3] = crelu(s.w);
    }
    #pragma unroll
    for (int it = 0; it < 16; it++) {
        const int idx = it * 256 + tid;
        const int j = idx >> 7, k = (idx & 127) * 4;
        *reinterpret_cast<float4*>(&W2s[j * TW2_STRIDE + k]) =
            *reinterpret_cast<const float4*>(&W2[j * 512 + k]);
    }
    __syncthreads();

    {
        const int row = wid;
        const float* w2r = W2s + lane * TW2_STRIDE;
        const float* cr  = comb + row * TCOMB_STRIDE;
        float a = b2[lane];
        #pragma unroll 8
        for (int k4 = 0; k4 < 128; k4++) {
            float4 w = *reinterpret_cast<const float4*>(&w2r[k4 * 4]);
            float4 c = *reinterpret_cast<const float4*>(&cr[k4 * 4]);
            a += w.x * c.x + w.y * c.y + w.z * c.z + w.w * c.w;
        }
        h1s[row * 32 + lane] = crelu(a);
        __syncwarp();
        float h2 = b3[lane];
        #pragma unroll
        for (int k = 0; k < 32; k++) h2 += W3[lane * 32 + k] * h1s[row * 32 + k];
        h2 = crelu(h2);
        float v = h2 * Wo[lane];
        #pragma unroll
        for (int o = 16; o; o >>= 1) v += __shfl_xor_sync(0xFFFFFFFFu, v, o);
        if (lane == 0) out[R0 + row] = crelu(v + bo[0]);
    }
}

extern "C" void kernel_launch(void* const* d_in, const int* in_sizes, int n_in,
                              void* d_out, int out_size)
{
    const float* xp  = (const float*)d_in[0];
    const float* xo  = (const float*)d_in[1];
    const float* W1p = (const float*)d_in[2];
    const float* b1p = (const float*)d_in[3];
    const float* W1o = (const float*)d_in[4];
    const float* b1o = (const float*)d_in[5];
    const float* W2  = (const float*)d_in[6];
    const float* b2  = (const float*)d_in[7];
    const float* W3  = (const float*)d_in[8];
    const float* b3  = (const float*)d_in[9];
    const float* Wo  = (const float*)d_in[10];
    const float* bo  = (const float*)d_in[11];

    static int grid_ft = 0;
    if (grid_ft == 0) {
        int smc = 148;
        cudaDeviceGetAttribute(&smc, cudaDevAttrMultiProcessorCount, 0);
        if (smc > 160) smc = 160;     // slot bound (<=4 partials per tile) needs chunk>=256
        if (smc < 64)  smc = 64;
        grid_ft = smc;
        cudaFuncSetAttribute(ft_kernel, cudaFuncAttributeMaxDynamicSharedMemorySize,
                             SMEM_BYTES);
        cudaFuncSetAttribute(reduce_tail, cudaFuncAttributeMaxDynamicSharedMemorySize,
                             TAIL_SMEM_BYTES);
    }
    zero_kernel<<<4096, 256>>>();
    ft_kernel<<<grid_ft, 256, SMEM_BYTES>>>(xp, xo, W1p, W1o);
    reduce_tail<<<256, 256, TAIL_SMEM_BYTES>>>(b1p, b1o, W2, b2, W3, b3, Wo, bo,
                                               (float*)d_out);
}

// round 9
// speedup vs baseline: 1.1038x; 1.1038x over previous
#include <cuda_runtime.h>
#include <cuda_fp16.h>
#include <cstdint>

#define BATCH   2048
#define INSZ    40960
#define KC      64
#define KSTPT   640                 // k-stages per tile (40960/64)
#define NTILE   64                  // 2 persp x 16 mt x 2 nt
#define TOTS    (NTILE * KSTPT)     // 40960 stage-units
#define ASTRW   36                  // smem row stride in words (64 fp16 + pad)
#define A_WORDS (128 * ASTRW)
#define BUF_WORDS (2 * A_WORDS)
#define SMEM_BYTES (2 * BUF_WORDS * 4)   // 73728

// tail smem carve (floats)
#define TW2_STRIDE 516
#define TW2_FLOATS (32 * TW2_STRIDE)
#define TCOMB_STRIDE 516
#define TCOMB_FLOATS (8 * TCOMB_STRIDE)
#define TH1_FLOATS (8 * 32)
#define TAIL_SMEM_BYTES ((TW2_FLOATS + TCOMB_FLOATS + TH1_FLOATS) * 4)

// partials: [tile][slot(4)][m_local(128)][n_local(128)] = 16 MB
__device__ float g_partial[(size_t)NTILE * 4 * 128 * 128];

__device__ __forceinline__ float crelu(float x) { return fminf(fmaxf(x, 0.f), 1.f); }

__device__ __forceinline__ uint32_t f2h2(float a, float b) {
    __half2 h = __floats2half2_rn(a, b);
    return *reinterpret_cast<uint32_t*>(&h);
}

__device__ __forceinline__ void mma16(float& c0, float& c1, float& c2, float& c3,
                                      uint32_t a0, uint32_t a1, uint32_t a2, uint32_t a3,
                                      uint32_t b0, uint32_t b1) {
    asm volatile(
        "mma.sync.aligned.m16n8k16.row.col.f32.f16.f16.f32 "
        "{%0,%1,%2,%3}, {%4,%5,%6,%7}, {%8,%9}, {%0,%1,%2,%3};"
        : "+f"(c0), "+f"(c1), "+f"(c2), "+f"(c3)
        : "r"(a0), "r"(a1), "r"(a2), "r"(a3), "r"(b0), "r"(b1));
}

// owner CTA of stage-unit s under contiguous even partition over G CTAs
__device__ __forceinline__ int owner_of(int s, int G) {
    return (int)((long)s * G / TOTS);
}

// ========== Kernel 1: FT GEMM, fp32-accum fp16 MMA, even stage-partition ==========
__global__ void __launch_bounds__(256, 1)
ft_kernel(const float* __restrict__ xp, const float* __restrict__ xo,
          const float* __restrict__ wp, const float* __restrict__ wo)
{
    extern __shared__ uint32_t sm[];
    const int tid = threadIdx.x, lane = tid & 31, wid = tid >> 5;
    const int G = gridDim.x, ib = blockIdx.x;
    int S = (int)((long)ib * TOTS / G);
    const int S_hi = (int)((long)(ib + 1) * TOTS / G);
    const uint32_t smb = (uint32_t)__cvta_generic_to_shared(sm);
    const int wm = (wid & 3) * 32;
    const int wn = (wid >> 2) * 64;

    while (S < S_hi) {
        const int t    = S / KSTPT;
        const int send = min(S_hi, (t + 1) * KSTPT);
        const int ks0  = S - t * KSTPT;
        const int len  = send - S;
        const int persp = t >> 5, mt = (t >> 1) & 15, nt = t & 1;
        const float* __restrict__ X = persp ? xo : xp;
        const float* __restrict__ W = persp ? wo : wp;
        const int m0 = mt * 128, n0 = nt * 128;
        const size_t kbase = (size_t)ks0 * KC;

        const float* aptr[8]; const float* bptr[8];
        uint32_t asw[8], bsw[8];
        #pragma unroll
        for (int j = 0; j < 8; j++) {
            int f = tid + j * 256, r = f >> 4, q = f & 15;
            aptr[j] = X + (size_t)(m0 + r) * INSZ + kbase + q * 4;
            bptr[j] = W + (size_t)(n0 + r) * INSZ + kbase + q * 4;
            asw[j] = smb + 4u * (r * ASTRW + q * 2);
            bsw[j] = smb + 4u * (A_WORDS + r * ASTRW + q * 2);
        }

        float acc[2][8][4];
        #pragma unroll
        for (int a = 0; a < 2; a++)
            #pragma unroll
            for (int b = 0; b < 8; b++)
                #pragma unroll
                for (int c = 0; c < 4; c++) acc[a][b][c] = 0.f;

        float4 ra[8], rb[8];
        // prologue: stage 0 -> buf0
        #pragma unroll
        for (int j = 0; j < 8; j++) ra[j] = *reinterpret_cast<const float4*>(aptr[j]);
        #pragma unroll
        for (int j = 0; j < 8; j++) rb[j] = *reinterpret_cast<const float4*>(bptr[j]);
        #pragma unroll
        for (int j = 0; j < 8; j++) {
            uint32_t u0 = f2h2(ra[j].x, ra[j].y), u1 = f2h2(ra[j].z, ra[j].w);
            asm volatile("st.shared.v2.b32 [%0], {%1,%2};" :: "r"(asw[j]), "r"(u0), "r"(u1) : "memory");
            uint32_t v0 = f2h2(rb[j].x, rb[j].y), v1 = f2h2(rb[j].z, rb[j].w);
            asm volatile("st.shared.v2.b32 [%0], {%1,%2};" :: "r"(bsw[j]), "r"(v0), "r"(v1) : "memory");
        }
        __syncthreads();
        if (len > 1) {
            #pragma unroll
            for (int j = 0; j < 8; j++) ra[j] = *reinterpret_cast<const float4*>(aptr[j] + KC);
            #pragma unroll
            for (int j = 0; j < 8; j++) rb[j] = *reinterpret_cast<const float4*>(bptr[j] + KC);
        }

        for (int s2 = 0; s2 < len; s2++) {
            const int buf = s2 & 1;
            // 1) STS stage s2+1 (regs loaded one stage ago) into the other buffer
            if (s2 + 1 < len) {
                const uint32_t boff = (uint32_t)((buf ^ 1) * BUF_WORDS * 4);
                #pragma unroll
                for (int j = 0; j < 8; j++) {
                    uint32_t u0 = f2h2(ra[j].x, ra[j].y), u1 = f2h2(ra[j].z, ra[j].w);
                    asm volatile("st.shared.v2.b32 [%0], {%1,%2};" :: "r"(asw[j] + boff), "r"(u0), "r"(u1) : "memory");
                    uint32_t v0 = f2h2(rb[j].x, rb[j].y), v1 = f2h2(rb[j].z, rb[j].w);
                    asm volatile("st.shared.v2.b32 [%0], {%1,%2};" :: "r"(bsw[j] + boff), "r"(v0), "r"(v1) : "memory");
                }
            }
            // 2) LDG for stage s2+2
            if (s2 + 2 < len) {
                const size_t ko = (size_t)(s2 + 2) * KC;
                #pragma unroll
                for (int j = 0; j < 8; j++) ra[j] = *reinterpret_cast<const float4*>(aptr[j] + ko);
                #pragma unroll
                for (int j = 0; j < 8; j++) rb[j] = *reinterpret_cast<const float4*>(bptr[j] + ko);
            }
            // 3) MMA over current buffer
            const uint32_t* sa = sm + buf * BUF_WORDS;
            const uint32_t* sb = sa + A_WORDS;
            #pragma unroll
            for (int kk = 0; kk < 4; kk++) {
                const int kw = kk * 8 + (lane & 3);
                uint32_t af[2][4], bf[8][2];
                #pragma unroll
                for (int mtl = 0; mtl < 2; mtl++) {
                    const int r = wm + mtl * 16 + (lane >> 2);
                    af[mtl][0] = sa[r * ASTRW + kw];
                    af[mtl][1] = sa[(r + 8) * ASTRW + kw];
                    af[mtl][2] = sa[r * ASTRW + kw + 4];
                    af[mtl][3] = sa[(r + 8) * ASTRW + kw + 4];
                }
                #pragma unroll
                for (int ntl = 0; ntl < 8; ntl++) {
                    const int rn = wn + ntl * 8 + (lane >> 2);
                    bf[ntl][0] = sb[rn * ASTRW + kw];
                    bf[ntl][1] = sb[rn * ASTRW + kw + 4];
                }
                #pragma unroll
                for (int mtl = 0; mtl < 2; mtl++)
                    #pragma unroll
                    for (int ntl = 0; ntl < 8; ntl++)
                        mma16(acc[mtl][ntl][0], acc[mtl][ntl][1],
                              acc[mtl][ntl][2], acc[mtl][ntl][3],
                              af[mtl][0], af[mtl][1], af[mtl][2], af[mtl][3],
                              bf[ntl][0], bf[ntl][1]);
            }
            __syncthreads();
        }

        // epilogue: deterministic slot = ib - owner(first stage of tile t)
        const int slot = ib - owner_of(t * KSTPT, G);   // 0..3
        float* gp = g_partial + ((size_t)t * 4 + slot) * 16384;
        #pragma unroll
        for (int mtl = 0; mtl < 2; mtl++) {
            const int ml = wm + mtl * 16 + (lane >> 2);
            #pragma unroll
            for (int ntl = 0; ntl < 8; ntl++) {
                const int col = wn + ntl * 8 + (lane & 3) * 2;
                *reinterpret_cast<float2*>(&gp[(size_t)ml * 128 + col]) =
                    make_float2(acc[mtl][ntl][0], acc[mtl][ntl][1]);
                *reinterpret_cast<float2*>(&gp[(size_t)(ml + 8) * 128 + col]) =
                    make_float2(acc[mtl][ntl][2], acc[mtl][ntl][3]);
            }
        }
        S = send;
    }
}

// ========== Kernel 2: fused nslots-reduce + bias + crelu + tail MLP ==========
__global__ void __launch_bounds__(256)
reduce_tail(const float* __restrict__ b1p, const float* __restrict__ b1o,
            const float* __restrict__ W2, const float* __restrict__ b2,
            const float* __restrict__ W3, const float* __restrict__ b3,
            const float* __restrict__ Wo, const float* __restrict__ bo,
            float* __restrict__ out, int G)
{
    extern __shared__ float ts[];
    float* W2s  = ts;                       // [32][516]
    float* comb = ts + TW2_FLOATS;          // [8][516]
    float* h1s  = comb + TCOMB_FLOATS;      // [8][32]
    const int tid = threadIdx.x, lane = tid & 31, wid = tid >> 5;
    const int R0 = blockIdx.x * 8;

    #pragma unroll
    for (int it = 0; it < 4; it++) {
        const int idx = it * 256 + tid;            // 8 rows x 128 f4
        const int row = idx >> 7, fq = idx & 127;
        const int m = R0 + row;
        const int f = fq * 4;
        const int persp = f >> 8;
        const int ntl = (f >> 7) & 1;
        const int c = f & 127;
        const int t = persp * 32 + (m >> 7) * 2 + ntl;
        // number of CTAs that contributed a slot to tile t (deterministic)
        const int o0 = (int)((long)t * KSTPT * G / TOTS);
        const int o1 = (int)(((long)t * KSTPT + KSTPT - 1) * G / TOTS);
        const int ns = o1 - o0 + 1;                // 1..4
        const float* gp = g_partial + (size_t)t * 4 * 16384 + (size_t)(m & 127) * 128 + c;
        float4 bv = (f < 256) ? *reinterpret_cast<const float4*>(&b1p[f])
                              : *reinterpret_cast<const float4*>(&b1o[f - 256]);
        float4 s = bv;
        for (int sl = 0; sl < ns; sl++) {
            float4 v = *reinterpret_cast<const float4*>(gp + (size_t)sl * 16384);
            s.x += v.x; s.y += v.y; s.z += v.z; s.w += v.w;
        }
        float* cc = comb + row * TCOMB_STRIDE + f;
        cc[0] = crelu(s.x); cc[1] = crelu(s.y); cc[2] = crelu(s.z); cc[3] = crelu(s.w);
    }
    #pragma unroll
    for (int it = 0; it < 16; it++) {
        const int idx = it * 256 + tid;
        const int j = idx >> 7, k = (idx & 127) * 4;
        *reinterpret_cast<float4*>(&W2s[j * TW2_STRIDE + k]) =
            *reinterpret_cast<const float4*>(&W2[j * 512 + k]);
    }
    __syncthreads();

    {
        const int row = wid;
        const float* w2r = W2s + lane * TW2_STRIDE;
        const float* cr  = comb + row * TCOMB_STRIDE;
        float a = b2[lane];
        #pragma unroll 8
        for (int k4 = 0; k4 < 128; k4++) {
            float4 w = *reinterpret_cast<const float4*>(&w2r[k4 * 4]);
            float4 c = *reinterpret_cast<const float4*>(&cr[k4 * 4]);
            a += w.x * c.x + w.y * c.y + w.z * c.z + w.w * c.w;
        }
        h1s[row * 32 + lane] = crelu(a);
        __syncwarp();
        float h2 = b3[lane];
        #pragma unroll
        for (int k = 0; k < 32; k++) h2 += W3[lane * 32 + k] * h1s[row * 32 + k];
        h2 = crelu(h2);
        float v = h2 * Wo[lane];
        #pragma unroll
        for (int o = 16; o; o >>= 1) v += __shfl_xor_sync(0xFFFFFFFFu, v, o);
        if (lane == 0) out[R0 + row] = crelu(v + bo[0]);
    }
}

extern "C" void kernel_launch(void* const* d_in, const int* in_sizes, int n_in,
                              void* d_out, int out_size)
{
    const float* xp  = (const float*)d_in[0];
    const float* xo  = (const float*)d_in[1];
    const float* W1p = (const float*)d_in[2];
    const float* b1p = (const float*)d_in[3];
    const float* W1o = (const float*)d_in[4];
    const float* b1o = (const float*)d_in[5];
    const float* W2  = (const float*)d_in[6];
    const float* b2  = (const float*)d_in[7];
    const float* W3  = (const float*)d_in[8];
    const float* b3  = (const float*)d_in[9];
    const float* Wo  = (const float*)d_in[10];
    const float* bo  = (const float*)d_in[11];

    static int grid_ft = 0;
    if (grid_ft == 0) {
        int smc = 148;
        cudaDeviceGetAttribute(&smc, cudaDevAttrMultiProcessorCount, 0);
        if (smc > 160) smc = 160;     // slot bound (<=4 partials per tile) needs chunk>=256
        if (smc < 64)  smc = 64;
        grid_ft = smc;
        cudaFuncSetAttribute(ft_kernel, cudaFuncAttributeMaxDynamicSharedMemorySize,
                             SMEM_BYTES);
        cudaFuncSetAttribute(reduce_tail, cudaFuncAttributeMaxDynamicSharedMemorySize,
                             TAIL_SMEM_BYTES);
    }
    ft_kernel<<<grid_ft, 256, SMEM_BYTES>>>(xp, xo, W1p, W1o);
    reduce_tail<<<256, 256, TAIL_SMEM_BYTES>>>(b1p, b1o, W2, b2, W3, b3, Wo, bo,
                                               (float*)d_out, grid_ft);
}